// round 11
// baseline (speedup 1.0000x reference)
#include <cuda_runtime.h>
#include <cuda_bf16.h>
#include <cstdint>
#include <cstddef>

// ---------------- problem constants ----------------
#define B_    32
#define S_    2048
#define C_    7
#define O_    512
#define KLOG  168          // real K, k = i*3+h, i = c*8+m
#define KP    176          // padded K (11 ksteps of 16)
#define NKS   11
#define TT    128          // t per tile (M)
#define OCH   128          // o per chunk (N)
#define NCHUNK 4
#define NSLOT 37           // 37*4 = 148 persistent CTAs
#define NTILE 512          // t-tiles per chunk (32 b * 16)
#define NTH   256

#define ROWB  368          // smem bf16 row stride in bytes (16B-aligned, conflict-free)
#define GROWW (KP/2)       // gmem z row in words (88)

// ---------------- smem byte layout (total ~185KB) ----------------
#define SM_BIAS  0                      // 512B
#define SM_AHI   512                    // 128*368 = 47104
#define SM_ALO   (SM_AHI + 47104)
#define SM_WHI   (SM_ALO + 47104)
#define SM_WLO   (SM_WHI + 47104)
#define SM_TOTAL (SM_WLO + 47104)       // 188928

// W pre-split: [hi|lo][o=512][k=176] bf16
__device__ __nv_bfloat16 g_Wb[2 * 512 * KP];
// z materialized: [hi|lo][b*2048+t][176] bf16  (46 MB scratch)
__device__ uint32_t g_z[2][B_ * S_ * GROWW];

__global__ void wsetup_kernel(const float* __restrict__ W) {
    int gid = blockIdx.x * blockDim.x + threadIdx.x;
    if (gid >= 512 * KP) return;
    int o = gid / KP, k = gid % KP;
    float w = (k < KLOG) ? W[o * KLOG + k] : 0.f;
    __nv_bfloat16 hi = __float2bfloat16(w);
    __nv_bfloat16 lo = __float2bfloat16(w - __bfloat162float(hi));
    g_Wb[gid] = hi;
    g_Wb[512 * KP + gid] = lo;
}

// build z (hi/lo bf16 pairs) for every (b, t, kpair)
__global__ void zprep_kernel(const float* __restrict__ x) {
    int gid = blockIdx.x * blockDim.x + threadIdx.x;
    if (gid >= B_ * S_ * GROWW) return;
    int q  = gid % GROWW;
    int bt = gid / GROWW;
    int tt = bt & (S_ - 1);
    int b  = bt >> 11;
    uint32_t hw = 0, lw = 0;
    #pragma unroll
    for (int half = 0; half < 2; ++half) {
        int k = 2 * q + half;
        float val = 0.f;
        if (k < KLOG) {
            int i = k / 3, h = k - 3 * i, m = i & 7, c = i >> 3;
            int s = (tt - 1 + h) & (S_ - 1);
            if (s >= KLOG)
                val = __ldg(&x[((size_t)b * S_ + (s - 24 * m)) * C_ + c]);
        }
        __nv_bfloat16 hi = __float2bfloat16(val);
        __nv_bfloat16 lo = __float2bfloat16(val - __bfloat162float(hi));
        hw |= (uint32_t)__bfloat16_as_ushort(hi) << (16 * half);
        lw |= (uint32_t)__bfloat16_as_ushort(lo) << (16 * half);
    }
    g_z[0][gid] = hw;
    g_z[1][gid] = lw;
}

// ---------------- PTX helpers ----------------
#define CP_COMMIT()  asm volatile("cp.async.commit_group;")
#define CP_WAIT0()   asm volatile("cp.async.wait_group 0;")
#define PAIR_BAR(id) asm volatile("bar.sync %0, 64;" :: "r"(id) : "memory")

#define LDSM4(r, addr) \
    asm volatile("ldmatrix.sync.aligned.m8n8.x4.shared.b16 {%0,%1,%2,%3}, [%4];" \
        : "=r"((r)[0]), "=r"((r)[1]), "=r"((r)[2]), "=r"((r)[3]) : "r"(addr))

#define MMA16816(d, a, b0, b1) \
    asm volatile("mma.sync.aligned.m16n8k16.row.col.f32.bf16.bf16.f32 " \
        "{%0,%1,%2,%3},{%4,%5,%6,%7},{%8,%9},{%0,%1,%2,%3};" \
        : "+f"((d)[0]), "+f"((d)[1]), "+f"((d)[2]), "+f"((d)[3]) \
        : "r"((a)[0]), "r"((a)[1]), "r"((a)[2]), "r"((a)[3]), "r"(b0), "r"(b1))

// prefetch of one half (hi or lo) of the pair's 32 A rows for one tile
__device__ __forceinline__ void prefetch_A_half(uint32_t sb, int warp_m, int lane,
                                                int half, int bb, int t0) {
    size_t grow0 = (size_t)bb * S_ + t0 + warp_m;
    const uint32_t base = sb + (half ? SM_ALO : SM_AHI);
    const uint32_t* src0 = g_z[half];
    #pragma unroll 1
    for (int j = 0; j < 22; ++j) {
        int f = j * 32 + lane;
        int row = f / 22;
        int seg = f - row * 22;
        const uint32_t* src = src0 + (grow0 + row) * GROWW + seg * 4;
        uint32_t dst = base + (uint32_t)(warp_m + row) * ROWB + seg * 16;
        asm volatile("cp.async.cg.shared.global [%0], [%1], 16;"
                     :: "r"(dst), "l"(src));
    }
}

__global__ __launch_bounds__(NTH, 1)
void conv_hmma_kernel(const float* __restrict__ bias,
                      float* __restrict__ out) {
    extern __shared__ char smem[];
    const uint32_t sb = (uint32_t)__cvta_generic_to_shared(smem);
    const int tid  = threadIdx.x;
    const int lane = tid & 31;
    const int wid  = tid >> 5;
    const int chunk = blockIdx.x & 3;
    const int slot  = blockIdx.x >> 2;
    const int ntiles = (NTILE - slot + NSLOT - 1) / NSLOT;

    float* biasS = (float*)(smem + SM_BIAS);
    for (int j = tid; j < OCH; j += NTH) biasS[j] = bias[chunk * OCH + j];

    // stage W (hi+lo) slice for this chunk: 2 x 128 rows x 22 x 16B
    {
        const char* wsrc = (const char*)g_Wb;
        for (int f = tid; f < 2 * 128 * 22; f += NTH) {
            int half = f / (128 * 22);
            int rem  = f - half * (128 * 22);
            int n = rem / 22, seg = rem - n * 22;
            const char* src = wsrc + (size_t)(half * 512 + chunk * OCH + n) * (KP * 2) + seg * 16;
            uint32_t dst = sb + (half ? SM_WLO : SM_WHI) + (uint32_t)n * ROWB + seg * 16;
            asm volatile("cp.async.cg.shared.global [%0], [%1], 16;"
                         :: "r"(dst), "l"(src));
        }
    }

    const int warp_m = (wid & 3) * 32;     // warps w and w+4 SHARE these A rows
    const int warp_n = (wid >> 2) * 64;
    const int ahalf  = wid >> 2;           // pair split: w loads hi, w+4 loads lo
    const int barid  = 1 + (wid & 3);      // pair-scoped named barrier

    // prefetch A for tile 0 (each pair member loads its half)
    {
        int tl = slot;
        prefetch_A_half(sb, warp_m, lane, ahalf, tl >> 4, (tl & 15) << 7);
    }
    CP_COMMIT();
    CP_WAIT0();
    __syncthreads();          // W + bias + everyone's A(0) visible

    // per-lane ldmatrix offsets
    const int jT = lane >> 3;
    const uint32_t aOff = (uint32_t)(warp_m + ((jT & 1) << 3) + (lane & 7)) * ROWB
                        + (uint32_t)((jT >> 1) << 4);
    uint32_t bOff[4];
    #pragma unroll
    for (int p = 0; p < 4; ++p)
        bOff[p] = (uint32_t)(warp_n + p * 16 + ((jT >> 1) << 3) + (lane & 7)) * ROWB
                + (uint32_t)((jT & 1) << 4);

    const int g  = lane >> 2;
    const int c2 = (lane & 3) * 2;

    for (int n = 0; n < ntiles; ++n) {
        const int tl = slot + n * NSLOT;
        const int bb = tl >> 4;
        const int t0 = (tl & 15) << 7;

        if (n) {
            CP_WAIT0();       // own half of A(n) landed
            PAIR_BAR(barid);  // partner's half landed too -> visible to pair
        }

        float acc[2][8][4];
        #pragma unroll
        for (int mt = 0; mt < 2; ++mt)
            #pragma unroll
            for (int nt = 0; nt < 8; ++nt)
                #pragma unroll
                for (int q = 0; q < 4; ++q) acc[mt][nt][q] = 0.f;

        // ---- software-pipelined k-loop: ping-pong fragment buffers ----
        uint32_t fAh0[2][4], fAh1[2][4], fAl0[2][4], fAl1[2][4];
        uint32_t fBh[2][4][4], fBl[2][4][4];

#define LOAD_FRAGS(bf, ks) do {                                          \
        uint32_t kb_ = (uint32_t)(ks) * 32u;                             \
        LDSM4(fAh0[bf], sb + SM_AHI + aOff + kb_);                       \
        LDSM4(fAh1[bf], sb + SM_AHI + aOff + 16 * ROWB + kb_);           \
        LDSM4(fAl0[bf], sb + SM_ALO + aOff + kb_);                       \
        LDSM4(fAl1[bf], sb + SM_ALO + aOff + 16 * ROWB + kb_);           \
        _Pragma("unroll")                                                \
        for (int p = 0; p < 4; ++p) {                                    \
            LDSM4(fBh[bf][p], sb + SM_WHI + bOff[p] + kb_);              \
            LDSM4(fBl[bf][p], sb + SM_WLO + bOff[p] + kb_);              \
        }                                                                \
    } while (0)

#define MMA_ALL(bf) do {                                                 \
        _Pragma("unroll")                                                \
        for (int nt = 0; nt < 8; ++nt) {                                 \
            uint32_t b0h = fBh[bf][nt >> 1][(nt & 1) << 1];              \
            uint32_t b1h = fBh[bf][nt >> 1][((nt & 1) << 1) + 1];        \
            uint32_t b0l = fBl[bf][nt >> 1][(nt & 1) << 1];              \
            uint32_t b1l = fBl[bf][nt >> 1][((nt & 1) << 1) + 1];        \
            MMA16816(acc[0][nt], fAh0[bf], b0h, b1h);                    \
            MMA16816(acc[1][nt], fAh1[bf], b0h, b1h);                    \
            MMA16816(acc[0][nt], fAl0[bf], b0h, b1h);                    \
            MMA16816(acc[1][nt], fAl1[bf], b0h, b1h);                    \
            MMA16816(acc[0][nt], fAh0[bf], b0l, b1l);                    \
            MMA16816(acc[1][nt], fAh1[bf], b0l, b1l);                    \
        }                                                                \
    } while (0)

        LOAD_FRAGS(0, 0);
        #pragma unroll 1
        for (int ks = 0; ks < NKS - 1; ks += 2) {
            LOAD_FRAGS(1, ks + 1);       // next kstep's frags, independent
            MMA_ALL(0);                  // current kstep's MMAs
            if (ks + 2 < NKS) LOAD_FRAGS(0, ks + 2);
            MMA_ALL(1);
        }
        MMA_ALL(0);                      // kstep 10 (loaded at ks=8 iteration)

#undef LOAD_FRAGS
#undef MMA_ALL

        // both pair members done READING A(n) before anyone overwrites it
        PAIR_BAR(barid);

        if (n + 1 < ntiles) {
            int tl1 = slot + (n + 1) * NSLOT;
            prefetch_A_half(sb, warp_m, lane, ahalf, tl1 >> 4, (tl1 & 15) << 7);
        }
        CP_COMMIT();

        // ---- epilogue: bias + store (overlaps the A prefetch) ----
        #pragma unroll
        for (int mt = 0; mt < 2; ++mt) {
            size_t row = (size_t)bb * S_ + t0 + warp_m + mt * 16 + g;
            #pragma unroll
            for (int nt = 0; nt < 8; ++nt) {
                int ncol = warp_n + nt * 8 + c2;
                float bi0 = biasS[ncol], bi1 = biasS[ncol + 1];
                float* p0 = out + row * O_ + chunk * OCH + ncol;
                *(float2*)p0 = make_float2(acc[mt][nt][0] + bi0,
                                           acc[mt][nt][1] + bi1);
                *(float2*)(p0 + 8 * O_) = make_float2(acc[mt][nt][2] + bi0,
                                                      acc[mt][nt][3] + bi1);
            }
        }
    }
}

extern "C" void kernel_launch(void* const* d_in, const int* in_sizes, int n_in,
                              void* d_out, int out_size) {
    const float* x    = (const float*)d_in[0];  // (32, 2048, 7)
    const float* W    = (const float*)d_in[1];  // (512, 56, 3)
    const float* bias = (const float*)d_in[2];  // (512,)
    float* out = (float*)d_out;                 // (32, 2048, 512)

    cudaFuncSetAttribute(conv_hmma_kernel,
                         cudaFuncAttributeMaxDynamicSharedMemorySize, SM_TOTAL);

    wsetup_kernel<<<(512 * KP + 255) / 256, 256>>>(W);
    zprep_kernel<<<(B_ * S_ * GROWW + 255) / 256, 256>>>(x);
    conv_hmma_kernel<<<NSLOT * NCHUNK, NTH, SM_TOTAL>>>(bias, out);
}

// round 12
// speedup vs baseline: 1.4151x; 1.4151x over previous
#include <cuda_runtime.h>
#include <cuda_bf16.h>
#include <cstdint>
#include <cstddef>

// ---------------- problem constants ----------------
#define B_    32
#define S_    2048
#define C_    7
#define O_    512
#define KLOG  168          // real K, k = i*3+h, i = c*8+m
#define KP    176          // padded K (11 ksteps of 16)
#define NKS   11
#define TT    128          // t per tile (M)
#define OCH   128          // o per chunk (N)
#define NCHUNK 4
#define NSLOT 37           // 37*4 = 148 persistent CTAs
#define NTILE 512          // t-tiles per chunk (32 b * 16)
#define NTH   128          // 4 warps, 64x64 tile each

#define ROWB  368          // smem bf16 row stride in bytes (16B-aligned, conflict-free)
#define GROWW (KP/2)       // gmem z row in words (88)

// ---------------- smem byte layout (total ~185KB) ----------------
#define SM_BIAS  0                      // 512B
#define SM_AHI   512                    // 128*368 = 47104
#define SM_ALO   (SM_AHI + 47104)
#define SM_WHI   (SM_ALO + 47104)
#define SM_WLO   (SM_WHI + 47104)
#define SM_TOTAL (SM_WLO + 47104)       // 188928

// W pre-split: [hi|lo][o=512][k=176] bf16
__device__ __nv_bfloat16 g_Wb[2 * 512 * KP];
// z materialized: [hi|lo][b*2048+t][176] bf16  (46 MB scratch)
__device__ uint32_t g_z[2][B_ * S_ * GROWW];

// fused prep: builds z for all (b,t,kpair) AND the split W (first 352 blocks)
__global__ void prep_kernel(const float* __restrict__ x,
                            const float* __restrict__ W) {
    int gid = blockIdx.x * blockDim.x + threadIdx.x;

    if (gid < 512 * KP) {            // W split part
        int o = gid / KP, k = gid % KP;
        float w = (k < KLOG) ? W[o * KLOG + k] : 0.f;
        __nv_bfloat16 hi = __float2bfloat16(w);
        __nv_bfloat16 lo = __float2bfloat16(w - __bfloat162float(hi));
        g_Wb[gid] = hi;
        g_Wb[512 * KP + gid] = lo;
    }

    if (gid < B_ * S_ * GROWW) {     // z part
        int q  = gid % GROWW;
        int bt = gid / GROWW;
        int tt = bt & (S_ - 1);
        int b  = bt >> 11;
        uint32_t hw = 0, lw = 0;
        #pragma unroll
        for (int half = 0; half < 2; ++half) {
            int k = 2 * q + half;
            float val = 0.f;
            if (k < KLOG) {
                int i = k / 3, h = k - 3 * i, m = i & 7, c = i >> 3;
                int s = (tt - 1 + h) & (S_ - 1);
                if (s >= KLOG)
                    val = __ldg(&x[((size_t)b * S_ + (s - 24 * m)) * C_ + c]);
            }
            __nv_bfloat16 hi = __float2bfloat16(val);
            __nv_bfloat16 lo = __float2bfloat16(val - __bfloat162float(hi));
            hw |= (uint32_t)__bfloat16_as_ushort(hi) << (16 * half);
            lw |= (uint32_t)__bfloat16_as_ushort(lo) << (16 * half);
        }
        g_z[0][gid] = hw;
        g_z[1][gid] = lw;
    }
}

// ---------------- PTX helpers ----------------
#define CP_COMMIT()  asm volatile("cp.async.commit_group;")
#define CP_WAIT0()   asm volatile("cp.async.wait_group 0;")
#define PAIR_BAR(id) asm volatile("bar.sync %0, 64;" :: "r"(id) : "memory")

#define LDSM4(r, addr) \
    asm volatile("ldmatrix.sync.aligned.m8n8.x4.shared.b16 {%0,%1,%2,%3}, [%4];" \
        : "=r"((r)[0]), "=r"((r)[1]), "=r"((r)[2]), "=r"((r)[3]) : "r"(addr))

#define MMA16816(d, a, b0, b1) \
    asm volatile("mma.sync.aligned.m16n8k16.row.col.f32.bf16.bf16.f32 " \
        "{%0,%1,%2,%3},{%4,%5,%6,%7},{%8,%9},{%0,%1,%2,%3};" \
        : "+f"((d)[0]), "+f"((d)[1]), "+f"((d)[2]), "+f"((d)[3]) \
        : "r"((a)[0]), "r"((a)[1]), "r"((a)[2]), "r"((a)[3]), "r"(b0), "r"(b1))

// prefetch one half (hi or lo) of a 64-row A strip for one tile
__device__ __forceinline__ void prefetch_A_half(uint32_t sb, int warp_m, int lane,
                                                int half, int bb, int t0) {
    size_t grow0 = (size_t)bb * S_ + t0 + warp_m;
    const uint32_t base = sb + (half ? SM_ALO : SM_AHI);
    const uint32_t* src0 = g_z[half];
    #pragma unroll 1
    for (int j = 0; j < 44; ++j) {          // 64 rows * 22 segs / 32 lanes
        int f = j * 32 + lane;
        int row = f / 22;
        int seg = f - row * 22;
        const uint32_t* src = src0 + (grow0 + row) * GROWW + seg * 4;
        uint32_t dst = base + (uint32_t)(warp_m + row) * ROWB + seg * 16;
        asm volatile("cp.async.cg.shared.global [%0], [%1], 16;"
                     :: "r"(dst), "l"(src));
    }
}

__global__ __launch_bounds__(NTH, 1)
void conv_hmma_kernel(const float* __restrict__ bias,
                      float* __restrict__ out) {
    extern __shared__ char smem[];
    const uint32_t sb = (uint32_t)__cvta_generic_to_shared(smem);
    const int tid  = threadIdx.x;
    const int lane = tid & 31;
    const int wid  = tid >> 5;              // 0..3
    const int chunk = blockIdx.x & 3;
    const int slot  = blockIdx.x >> 2;
    const int ntiles = (NTILE - slot + NSLOT - 1) / NSLOT;

    float* biasS = (float*)(smem + SM_BIAS);
    for (int j = tid; j < OCH; j += NTH) biasS[j] = bias[chunk * OCH + j];

    // stage W (hi+lo) slice for this chunk: 2 x 128 rows x 22 x 16B
    {
        const char* wsrc = (const char*)g_Wb;
        for (int f = tid; f < 2 * 128 * 22; f += NTH) {
            int half = f / (128 * 22);
            int rem  = f - half * (128 * 22);
            int n = rem / 22, seg = rem - n * 22;
            const char* src = wsrc + (size_t)(half * 512 + chunk * OCH + n) * (KP * 2) + seg * 16;
            uint32_t dst = sb + (half ? SM_WLO : SM_WHI) + (uint32_t)n * ROWB + seg * 16;
            asm volatile("cp.async.cg.shared.global [%0], [%1], 16;"
                         :: "r"(dst), "l"(src));
        }
    }

    const int warp_m = (wid & 1) * 64;      // warps {0,2} share m0, {1,3} share m64
    const int warp_n = (wid >> 1) * 64;
    const int ahalf  = wid >> 1;            // pair split: one member hi, other lo
    const int barid  = 1 + (wid & 1);       // pair-scoped named barrier

    // prefetch A strip for tile 0 (each pair member loads its half)
    {
        int tl = slot;
        prefetch_A_half(sb, warp_m, lane, ahalf, tl >> 4, (tl & 15) << 7);
    }
    CP_COMMIT();
    CP_WAIT0();
    __syncthreads();          // W + bias + A(0) visible

    // per-lane ldmatrix offsets
    const int jT = lane >> 3;
    const uint32_t aOff = (uint32_t)(warp_m + ((jT & 1) << 3) + (lane & 7)) * ROWB
                        + (uint32_t)((jT >> 1) << 4);
    uint32_t bOff[4];
    #pragma unroll
    for (int p = 0; p < 4; ++p)
        bOff[p] = (uint32_t)(warp_n + p * 16 + ((jT >> 1) << 3) + (lane & 7)) * ROWB
                + (uint32_t)((jT & 1) << 4);

    const int g  = lane >> 2;
    const int c2 = (lane & 3) * 2;

    for (int n = 0; n < ntiles; ++n) {
        const int tl = slot + n * NSLOT;
        const int bb = tl >> 4;
        const int t0 = (tl & 15) << 7;

        if (n) {
            CP_WAIT0();       // own half of A(n) landed
            PAIR_BAR(barid);  // partner's half landed too
        }

        float acc[4][8][4];
        #pragma unroll
        for (int mt = 0; mt < 4; ++mt)
            #pragma unroll
            for (int nt = 0; nt < 8; ++nt)
                #pragma unroll
                for (int q = 0; q < 4; ++q) acc[mt][nt][q] = 0.f;

        #pragma unroll 1
        for (int ks = 0; ks < NKS; ++ks) {
            uint32_t kb = (uint32_t)ks * 32u;

            // phase 1 frags: A hi+lo (4 m16-frags each) and B hi
            uint32_t Ah[4][4], Al[4][4], Bf[4][4];
            #pragma unroll
            for (int mt = 0; mt < 4; ++mt) {
                LDSM4(Ah[mt], sb + SM_AHI + aOff + (uint32_t)mt * (16 * ROWB) + kb);
                LDSM4(Al[mt], sb + SM_ALO + aOff + (uint32_t)mt * (16 * ROWB) + kb);
            }
            #pragma unroll
            for (int p = 0; p < 4; ++p)
                LDSM4(Bf[p], sb + SM_WHI + bOff[p] + kb);

            // hi*hi + lo*hi  (64 MMAs)
            #pragma unroll
            for (int nt = 0; nt < 8; ++nt) {
                uint32_t b0 = Bf[nt >> 1][(nt & 1) << 1];
                uint32_t b1 = Bf[nt >> 1][((nt & 1) << 1) + 1];
                #pragma unroll
                for (int mt = 0; mt < 4; ++mt) {
                    MMA16816(acc[mt][nt], Ah[mt], b0, b1);
                    MMA16816(acc[mt][nt], Al[mt], b0, b1);
                }
            }

            // phase 2: B lo (Al/Bh ranges now dead), hi*lo (32 MMAs)
            uint32_t Bl[4][4];
            #pragma unroll
            for (int p = 0; p < 4; ++p)
                LDSM4(Bl[p], sb + SM_WLO + bOff[p] + kb);
            #pragma unroll
            for (int nt = 0; nt < 8; ++nt) {
                uint32_t b0 = Bl[nt >> 1][(nt & 1) << 1];
                uint32_t b1 = Bl[nt >> 1][((nt & 1) << 1) + 1];
                #pragma unroll
                for (int mt = 0; mt < 4; ++mt)
                    MMA16816(acc[mt][nt], Ah[mt], b0, b1);
            }
        }

        // both pair members done READING A(n) before anyone overwrites it
        PAIR_BAR(barid);

        if (n + 1 < ntiles) {
            int tl1 = slot + (n + 1) * NSLOT;
            prefetch_A_half(sb, warp_m, lane, ahalf, tl1 >> 4, (tl1 & 15) << 7);
        }
        CP_COMMIT();

        // ---- epilogue: bias + store (overlaps the A prefetch) ----
        #pragma unroll
        for (int mt = 0; mt < 4; ++mt) {
            size_t row = (size_t)bb * S_ + t0 + warp_m + mt * 16 + g;
            #pragma unroll
            for (int nt = 0; nt < 8; ++nt) {
                int ncol = warp_n + nt * 8 + c2;
                float bi0 = biasS[ncol], bi1 = biasS[ncol + 1];
                float* p0 = out + row * O_ + chunk * OCH + ncol;
                *(float2*)p0 = make_float2(acc[mt][nt][0] + bi0,
                                           acc[mt][nt][1] + bi1);
                *(float2*)(p0 + 8 * O_) = make_float2(acc[mt][nt][2] + bi0,
                                                      acc[mt][nt][3] + bi1);
            }
        }
    }
}

extern "C" void kernel_launch(void* const* d_in, const int* in_sizes, int n_in,
                              void* d_out, int out_size) {
    const float* x    = (const float*)d_in[0];  // (32, 2048, 7)
    const float* W    = (const float*)d_in[1];  // (512, 56, 3)
    const float* bias = (const float*)d_in[2];  // (512,)
    float* out = (float*)d_out;                 // (32, 2048, 512)

    cudaFuncSetAttribute(conv_hmma_kernel,
                         cudaFuncAttributeMaxDynamicSharedMemorySize, SM_TOTAL);

    prep_kernel<<<(B_ * S_ * GROWW + 255) / 256, 256>>>(x, W);
    conv_hmma_kernel<<<NSLOT * NCHUNK, NTH, SM_TOTAL>>>(bias, out);
}

// round 13
// speedup vs baseline: 1.6085x; 1.1367x over previous
#include <cuda_runtime.h>
#include <cuda_bf16.h>
#include <cstdint>
#include <cstddef>

// ---------------- problem constants ----------------
#define B_    32
#define S_    2048
#define C_    7
#define O_    512
#define KLOG  168          // real K, k = i*3+h, i = c*8+m
#define KP    176          // padded K (11 ksteps of 16)
#define NKS   11
#define TT    128          // t per tile (M)
#define OCH   128          // o per chunk (N)
#define NCHUNK 4
#define NSLOT 37           // 37*4 = 148 persistent CTAs
#define NTILE 512          // t-tiles per chunk (32 b * 16)
#define NTH   256

#define ROWB  368          // smem bf16 row stride in bytes (16B-aligned, conflict-free)
#define GROWW (KP/2)       // gmem z row in words (88)

#define XSROWS 298
#define XSN   (XSROWS*C_)  // 2086 floats

// ---------------- smem byte layout (main kernel, ~185KB) ----------------
#define SM_BIAS  0                      // 512B
#define SM_AHI   512                    // 128*368 = 47104
#define SM_ALO   (SM_AHI + 47104)
#define SM_WHI   (SM_ALO + 47104)
#define SM_WLO   (SM_WHI + 47104)
#define SM_TOTAL (SM_WLO + 47104)       // 188928

// W pre-split: [hi|lo][o=512][k=176] bf16
__device__ __nv_bfloat16 g_Wb[2 * 512 * KP];
// z materialized: [hi|lo][b*2048+t][176] bf16  (46 MB scratch)
__device__ uint32_t g_z[2][B_ * S_ * GROWW];

// ---------------- prep: smem-staged z build + W split ----------------
// grid (16, 32), block 256. CTA (tx, bb) builds z rows [bb, tx*128 .. +127].
__global__ __launch_bounds__(NTH, 4)
void zprep_kernel(const float* __restrict__ x, const float* __restrict__ W) {
    __shared__ float xs[XSN];
    __shared__ int   koff[KP];
    __shared__ int   kh[KP];

    const int tid = threadIdx.x;
    const int t0  = blockIdx.x << 7;
    const int bb  = blockIdx.y;

    // coalesced stage of the modular x window (proven in R5)
    {
        const float* xb = x + (size_t)bb * S_ * C_;
        int g0 = ((t0 - (KLOG + 1)) & (S_ - 1)) * C_;
        #pragma unroll
        for (int f = tid; f < XSN; f += NTH) {
            int g = g0 + f;
            if (g >= S_ * C_) g -= S_ * C_;
            xs[f] = __ldg(&xb[g]);
        }
    }
    if (tid < KP) {
        int k = tid, i = k / 3, h = k - 3 * i, m = i & 7, c = i >> 3;
        koff[k] = (k < KLOG) ? ((h + KLOG - 24 * m) * C_ + c) : 0;
        kh[k]   = (k < KLOG) ? h : 3;       // sentinel bit 3 of vm is always 0
    }

    // W split, done by the tx==0 CTAs (32 CTAs x 16 o-rows each)
    if (blockIdx.x == 0) {
        for (int e = tid; e < 16 * KP; e += NTH) {
            int o = (bb << 4) + e / KP;
            int k = e % KP;
            float w = (k < KLOG) ? __ldg(&W[o * KLOG + k]) : 0.f;
            __nv_bfloat16 hi = __float2bfloat16(w);
            __nv_bfloat16 lo = __float2bfloat16(w - __bfloat162float(hi));
            g_Wb[o * KP + k] = hi;
            g_Wb[512 * KP + o * KP + k] = lo;
        }
    }
    __syncthreads();

    // build 128 z rows x 88 word-pairs; stores fully coalesced
    const size_t obase = ((size_t)bb * S_ + t0) * GROWW;
    for (int e = tid; e < TT * GROWW; e += NTH) {
        int r = e / GROWW;
        int q = e - r * GROWW;
        int s = t0 + r - 1;
        uint32_t vm = 0;
        if (((s)     & (S_ - 1)) >= KLOG) vm |= 1;
        if (((s + 1) & (S_ - 1)) >= KLOG) vm |= 2;
        if (((s + 2) & (S_ - 1)) >= KLOG) vm |= 4;
        const float* xr = xs + r * C_;
        int k0 = 2 * q, k1 = k0 + 1;
        float v0 = ((vm >> kh[k0]) & 1) ? xr[koff[k0]] : 0.f;
        float v1 = ((vm >> kh[k1]) & 1) ? xr[koff[k1]] : 0.f;
        __nv_bfloat16 h0 = __float2bfloat16(v0), h1 = __float2bfloat16(v1);
        __nv_bfloat16 l0 = __float2bfloat16(v0 - __bfloat162float(h0));
        __nv_bfloat16 l1 = __float2bfloat16(v1 - __bfloat162float(h1));
        uint32_t hw = (uint32_t)__bfloat16_as_ushort(h0)
                    | ((uint32_t)__bfloat16_as_ushort(h1) << 16);
        uint32_t lw = (uint32_t)__bfloat16_as_ushort(l0)
                    | ((uint32_t)__bfloat16_as_ushort(l1) << 16);
        g_z[0][obase + e] = hw;
        g_z[1][obase + e] = lw;
    }
}

// ---------------- PTX helpers ----------------
#define CP_COMMIT()  asm volatile("cp.async.commit_group;")
#define CP_WAIT0()   asm volatile("cp.async.wait_group 0;")
#define PAIR_BAR(id) asm volatile("bar.sync %0, 64;" :: "r"(id) : "memory")

#define LDSM4(r, addr) \
    asm volatile("ldmatrix.sync.aligned.m8n8.x4.shared.b16 {%0,%1,%2,%3}, [%4];" \
        : "=r"((r)[0]), "=r"((r)[1]), "=r"((r)[2]), "=r"((r)[3]) : "r"(addr))

#define MMA16816(d, a, b0, b1) \
    asm volatile("mma.sync.aligned.m16n8k16.row.col.f32.bf16.bf16.f32 " \
        "{%0,%1,%2,%3},{%4,%5,%6,%7},{%8,%9},{%0,%1,%2,%3};" \
        : "+f"((d)[0]), "+f"((d)[1]), "+f"((d)[2]), "+f"((d)[3]) \
        : "r"((a)[0]), "r"((a)[1]), "r"((a)[2]), "r"((a)[3]), "r"(b0), "r"(b1))

// prefetch of one half (hi or lo) of the pair's 32 A rows for one tile
__device__ __forceinline__ void prefetch_A_half(uint32_t sb, int warp_m, int lane,
                                                int half, int bb, int t0) {
    size_t grow0 = (size_t)bb * S_ + t0 + warp_m;
    const uint32_t base = sb + (half ? SM_ALO : SM_AHI);
    const uint32_t* src0 = g_z[half];
    #pragma unroll 1
    for (int j = 0; j < 22; ++j) {
        int f = j * 32 + lane;
        int row = f / 22;
        int seg = f - row * 22;
        const uint32_t* src = src0 + (grow0 + row) * GROWW + seg * 4;
        uint32_t dst = base + (uint32_t)(warp_m + row) * ROWB + seg * 16;
        asm volatile("cp.async.cg.shared.global [%0], [%1], 16;"
                     :: "r"(dst), "l"(src));
    }
}

__global__ __launch_bounds__(NTH, 1)
void conv_hmma_kernel(const float* __restrict__ bias,
                      float* __restrict__ out) {
    extern __shared__ char smem[];
    const uint32_t sb = (uint32_t)__cvta_generic_to_shared(smem);
    const int tid  = threadIdx.x;
    const int lane = tid & 31;
    const int wid  = tid >> 5;
    const int chunk = blockIdx.x & 3;
    const int slot  = blockIdx.x >> 2;
    const int ntiles = (NTILE - slot + NSLOT - 1) / NSLOT;

    float* biasS = (float*)(smem + SM_BIAS);
    for (int j = tid; j < OCH; j += NTH) biasS[j] = bias[chunk * OCH + j];

    // stage W (hi+lo) slice for this chunk: 2 x 128 rows x 22 x 16B
    {
        const char* wsrc = (const char*)g_Wb;
        for (int f = tid; f < 2 * 128 * 22; f += NTH) {
            int half = f / (128 * 22);
            int rem  = f - half * (128 * 22);
            int n = rem / 22, seg = rem - n * 22;
            const char* src = wsrc + (size_t)(half * 512 + chunk * OCH + n) * (KP * 2) + seg * 16;
            uint32_t dst = sb + (half ? SM_WLO : SM_WHI) + (uint32_t)n * ROWB + seg * 16;
            asm volatile("cp.async.cg.shared.global [%0], [%1], 16;"
                         :: "r"(dst), "l"(src));
        }
    }

    const int warp_m = (wid & 3) * 32;     // warps w and w+4 SHARE these A rows
    const int warp_n = (wid >> 2) * 64;
    const int ahalf  = wid >> 2;           // pair split: w loads hi, w+4 loads lo
    const int barid  = 1 + (wid & 3);      // pair-scoped named barrier

    // prefetch A for tile 0 (each pair member loads its half)
    {
        int tl = slot;
        prefetch_A_half(sb, warp_m, lane, ahalf, tl >> 4, (tl & 15) << 7);
    }
    CP_COMMIT();
    CP_WAIT0();
    __syncthreads();          // W + bias + everyone's A(0) visible

    // per-lane ldmatrix offsets
    const int jT = lane >> 3;
    const uint32_t aOff = (uint32_t)(warp_m + ((jT & 1) << 3) + (lane & 7)) * ROWB
                        + (uint32_t)((jT >> 1) << 4);
    uint32_t bOff[4];
    #pragma unroll
    for (int p = 0; p < 4; ++p)
        bOff[p] = (uint32_t)(warp_n + p * 16 + ((jT >> 1) << 3) + (lane & 7)) * ROWB
                + (uint32_t)((jT & 1) << 4);

    const int g  = lane >> 2;
    const int c2 = (lane & 3) * 2;

    for (int n = 0; n < ntiles; ++n) {
        const int tl = slot + n * NSLOT;
        const int bb = tl >> 4;
        const int t0 = (tl & 15) << 7;

        if (n) {
            CP_WAIT0();       // own half of A(n) landed
            PAIR_BAR(barid);  // partner's half landed too -> visible to pair
        }

        float acc[2][8][4];
        #pragma unroll
        for (int mt = 0; mt < 2; ++mt)
            #pragma unroll
            for (int nt = 0; nt < 8; ++nt)
                #pragma unroll
                for (int q = 0; q < 4; ++q) acc[mt][nt][q] = 0.f;

        #pragma unroll 1
        for (int ks = 0; ks < NKS; ++ks) {
            uint32_t kb = (uint32_t)ks * 32u;
            uint32_t Ah0[4], Ah1[4], Al0[4], Al1[4];
            LDSM4(Ah0, sb + SM_AHI + aOff + kb);
            LDSM4(Ah1, sb + SM_AHI + aOff + 16 * ROWB + kb);
            LDSM4(Al0, sb + SM_ALO + aOff + kb);
            LDSM4(Al1, sb + SM_ALO + aOff + 16 * ROWB + kb);
            uint32_t Bh[4][4], Bl[4][4];
            #pragma unroll
            for (int p = 0; p < 4; ++p) {
                LDSM4(Bh[p], sb + SM_WHI + bOff[p] + kb);
                LDSM4(Bl[p], sb + SM_WLO + bOff[p] + kb);
            }
            #pragma unroll
            for (int nt = 0; nt < 8; ++nt) {
                uint32_t b0h = Bh[nt >> 1][(nt & 1) << 1];
                uint32_t b1h = Bh[nt >> 1][((nt & 1) << 1) + 1];
                uint32_t b0l = Bl[nt >> 1][(nt & 1) << 1];
                uint32_t b1l = Bl[nt >> 1][((nt & 1) << 1) + 1];
                MMA16816(acc[0][nt], Ah0, b0h, b1h);
                MMA16816(acc[1][nt], Ah1, b0h, b1h);
                MMA16816(acc[0][nt], Al0, b0h, b1h);
                MMA16816(acc[1][nt], Al1, b0h, b1h);
                MMA16816(acc[0][nt], Ah0, b0l, b1l);
                MMA16816(acc[1][nt], Ah1, b0l, b1l);
            }
        }

        // both pair members done READING A(n) before anyone overwrites it
        PAIR_BAR(barid);

        if (n + 1 < ntiles) {
            int tl1 = slot + (n + 1) * NSLOT;
            prefetch_A_half(sb, warp_m, lane, ahalf, tl1 >> 4, (tl1 & 15) << 7);
        }
        CP_COMMIT();

        // ---- epilogue: bias + store (overlaps the A prefetch) ----
        #pragma unroll
        for (int mt = 0; mt < 2; ++mt) {
            size_t row = (size_t)bb * S_ + t0 + warp_m + mt * 16 + g;
            #pragma unroll
            for (int nt = 0; nt < 8; ++nt) {
                int ncol = warp_n + nt * 8 + c2;
                float bi0 = biasS[ncol], bi1 = biasS[ncol + 1];
                float* p0 = out + row * O_ + chunk * OCH + ncol;
                *(float2*)p0 = make_float2(acc[mt][nt][0] + bi0,
                                           acc[mt][nt][1] + bi1);
                *(float2*)(p0 + 8 * O_) = make_float2(acc[mt][nt][2] + bi0,
                                                      acc[mt][nt][3] + bi1);
            }
        }
    }
}

extern "C" void kernel_launch(void* const* d_in, const int* in_sizes, int n_in,
                              void* d_out, int out_size) {
    const float* x    = (const float*)d_in[0];  // (32, 2048, 7)
    const float* W    = (const float*)d_in[1];  // (512, 56, 3)
    const float* bias = (const float*)d_in[2];  // (512,)
    float* out = (float*)d_out;                 // (32, 2048, 512)

    cudaFuncSetAttribute(conv_hmma_kernel,
                         cudaFuncAttributeMaxDynamicSharedMemorySize, SM_TOTAL);

    dim3 pgrid(S_ / TT, B_);   // (16, 32)
    zprep_kernel<<<pgrid, NTH>>>(x, W);
    conv_hmma_kernel<<<NSLOT * NCHUNK, NTH, SM_TOTAL>>>(bias, out);
}

// round 14
// speedup vs baseline: 1.6475x; 1.0243x over previous
#include <cuda_runtime.h>
#include <cuda_bf16.h>
#include <cstdint>
#include <cstddef>

// ---------------- problem constants ----------------
#define B_    32
#define S_    2048
#define C_    7
#define O_    512
#define KLOG  168          // real K, k = i*3+h, i = c*8+m
#define KP    176          // padded K (11 ksteps of 16)
#define NKS   11
#define TT    128          // t per tile (M)
#define OCH   128          // o per chunk (N)
#define NCHUNK 4
#define NSLOT 74           // 74*4 = 296 CTAs = 2/SM
#define NTILE 512          // t-tiles per chunk (32 b * 16)
#define NTH   256

#define ROWB  368          // smem bf16 row stride for W (16B-aligned, conflict-free)

#define XSROWS 298
#define XSN   (XSROWS*C_)  // 2086 floats

// ---------------- main-kernel smem (94.7KB -> 2 CTAs/SM) ----------------
#define SM_BIAS  0                      // 512B
#define SM_WHI   512                    // 128*368 = 47104
#define SM_WLO   (SM_WHI + 47104)
#define SM_TOTAL (SM_WLO + 47104)       // 94720

// W pre-split: [hi|lo][o=512][k=176] bf16
__device__ __nv_bfloat16 g_Wb[2 * 512 * KP];
// z in m16n8k16 A-FRAGMENT order:
//   g_zf[half][ (bt*8 + mb)*11 + ks ][lane] : uint4 = frag words r0..r3
//   bt = b*16 + tile (0..511), mb = m16-block (0..7), ks = kstep (0..10)
__device__ uint4 g_zf[2][NTILE * 8 * NKS * 32];

// ---------------- prep: smem-staged, writes fragment-ordered z + W split ----
__global__ __launch_bounds__(NTH, 4)
void zprep_kernel(const float* __restrict__ x, const float* __restrict__ W) {
    __shared__ float xs[XSN];
    __shared__ int   koff[KP];
    __shared__ int   kh[KP];

    const int tid = threadIdx.x;
    const int t0  = blockIdx.x << 7;
    const int bb  = blockIdx.y;
    const int bt  = (bb << 4) + blockIdx.x;

    // coalesced stage of the modular x window (proven R5/R13)
    {
        const float* xb = x + (size_t)bb * S_ * C_;
        int g0 = ((t0 - (KLOG + 1)) & (S_ - 1)) * C_;
        #pragma unroll
        for (int f = tid; f < XSN; f += NTH) {
            int g = g0 + f;
            if (g >= S_ * C_) g -= S_ * C_;
            xs[f] = __ldg(&xb[g]);
        }
    }
    if (tid < KP) {
        int k = tid, i = k / 3, h = k - 3 * i, m = i & 7, c = i >> 3;
        koff[k] = (k < KLOG) ? ((h + KLOG - 24 * m) * C_ + c) : 0;
        kh[k]   = (k < KLOG) ? h : 3;       // sentinel: vm bit 3 always 0
    }

    // W split, done by the tx==0 CTAs (32 CTAs x 16 o-rows each)
    if (blockIdx.x == 0) {
        for (int e = tid; e < 16 * KP; e += NTH) {
            int o = (bb << 4) + e / KP;
            int k = e % KP;
            float w = (k < KLOG) ? __ldg(&W[o * KLOG + k]) : 0.f;
            __nv_bfloat16 hi = __float2bfloat16(w);
            __nv_bfloat16 lo = __float2bfloat16(w - __bfloat162float(hi));
            g_Wb[o * KP + k] = hi;
            g_Wb[512 * KP + o * KP + k] = lo;
        }
    }
    __syncthreads();

    // build fragments: task = (mb, ks, lane) -> one uint4 per half
    // frag word r of lane (g=lane>>2, tg=lane&3) at (mb, ks):
    //   r0: row 16mb+g,   k 16ks+2tg, +1       r1: row 16mb+8+g, same k
    //   r2: row 16mb+g,   k 16ks+8+2tg, +1     r3: row 16mb+8+g, k+8
    for (int e = tid; e < 8 * NKS * 32; e += NTH) {
        int lane = e & 31;
        int rest = e >> 5;
        int ks = rest % NKS;
        int mb = rest / NKS;
        int g  = lane >> 2, tg = lane & 3;
        int lrA = (mb << 4) + g;           // local z row (0..127)
        int lrB = lrA + 8;
        // valid masks for the two rows
        uint32_t vmA = 0, vmB = 0;
        {
            int sA = t0 + lrA - 1, sB = t0 + lrB - 1;
            #pragma unroll
            for (int h = 0; h < 3; ++h) {
                if (((sA + h) & (S_ - 1)) >= KLOG) vmA |= (1u << h);
                if (((sB + h) & (S_ - 1)) >= KLOG) vmB |= (1u << h);
            }
        }
        const float* xrA = xs + lrA * C_;
        const float* xrB = xs + lrB * C_;
        int kb = (ks << 4) + (tg << 1);
        uint32_t hiw[4], low[4];
        #pragma unroll
        for (int r = 0; r < 4; ++r) {
            int k0 = kb + ((r >> 1) << 3);      // +8 for r2,r3
            int k1 = k0 + 1;
            const float* xr = (r & 1) ? xrB : xrA;
            uint32_t vm = (r & 1) ? vmB : vmA;
            float v0 = ((vm >> kh[k0]) & 1) ? xr[koff[k0]] : 0.f;
            float v1 = ((vm >> kh[k1]) & 1) ? xr[koff[k1]] : 0.f;
            __nv_bfloat16 h0 = __float2bfloat16(v0), h1 = __float2bfloat16(v1);
            __nv_bfloat16 l0 = __float2bfloat16(v0 - __bfloat162float(h0));
            __nv_bfloat16 l1 = __float2bfloat16(v1 - __bfloat162float(h1));
            hiw[r] = (uint32_t)__bfloat16_as_ushort(h0)
                   | ((uint32_t)__bfloat16_as_ushort(h1) << 16);
            low[r] = (uint32_t)__bfloat16_as_ushort(l0)
                   | ((uint32_t)__bfloat16_as_ushort(l1) << 16);
        }
        uint32_t idx = (uint32_t)((bt * 8 + mb) * NKS + ks) * 32 + lane;
        g_zf[0][idx] = make_uint4(hiw[0], hiw[1], hiw[2], hiw[3]);
        g_zf[1][idx] = make_uint4(low[0], low[1], low[2], low[3]);
    }
}

// ---------------- PTX helpers ----------------
#define CP_COMMIT()  asm volatile("cp.async.commit_group;")
#define CP_WAIT0()   asm volatile("cp.async.wait_group 0;")

#define LDSM4(r, addr) \
    asm volatile("ldmatrix.sync.aligned.m8n8.x4.shared.b16 {%0,%1,%2,%3}, [%4];" \
        : "=r"((r)[0]), "=r"((r)[1]), "=r"((r)[2]), "=r"((r)[3]) : "r"(addr))

#define MMA16816V(d, av, b0, b1) \
    asm volatile("mma.sync.aligned.m16n8k16.row.col.f32.bf16.bf16.f32 " \
        "{%0,%1,%2,%3},{%4,%5,%6,%7},{%8,%9},{%0,%1,%2,%3};" \
        : "+f"((d)[0]), "+f"((d)[1]), "+f"((d)[2]), "+f"((d)[3]) \
        : "r"((av).x), "r"((av).y), "r"((av).z), "r"((av).w), "r"(b0), "r"(b1))

__global__ __launch_bounds__(NTH, 2)
void conv_hmma_kernel(const float* __restrict__ bias,
                      float* __restrict__ out) {
    extern __shared__ char smem[];
    const uint32_t sb = (uint32_t)__cvta_generic_to_shared(smem);
    const int tid  = threadIdx.x;
    const int lane = tid & 31;
    const int wid  = tid >> 5;
    const int chunk = blockIdx.x & 3;
    const int slot  = blockIdx.x >> 2;
    const int ntiles = (NTILE - slot + NSLOT - 1) / NSLOT;

    float* biasS = (float*)(smem + SM_BIAS);
    for (int j = tid; j < OCH; j += NTH) biasS[j] = bias[chunk * OCH + j];

    // stage W (hi+lo) slice for this chunk: 2 x 128 rows x 22 x 16B
    {
        const char* wsrc = (const char*)g_Wb;
        for (int f = tid; f < 2 * 128 * 22; f += NTH) {
            int half = f / (128 * 22);
            int rem  = f - half * (128 * 22);
            int n = rem / 22, seg = rem - n * 22;
            const char* src = wsrc + (size_t)(half * 512 + chunk * OCH + n) * (KP * 2) + seg * 16;
            uint32_t dst = sb + (half ? SM_WLO : SM_WHI) + (uint32_t)n * ROWB + seg * 16;
            asm volatile("cp.async.cg.shared.global [%0], [%1], 16;"
                         :: "r"(dst), "l"(src));
        }
    }
    CP_COMMIT();
    CP_WAIT0();
    __syncthreads();          // W + bias visible; the ONLY barrier

    const int warp_m = (wid & 3) * 32;
    const int warp_n = (wid >> 2) * 64;
    const int mb0    = 2 * (wid & 3);     // first m16-block of this warp

    // B ldmatrix per-lane offsets (unchanged from R13)
    const int jT = lane >> 3;
    uint32_t bOff[4];
    #pragma unroll
    for (int p = 0; p < 4; ++p)
        bOff[p] = (uint32_t)(warp_n + p * 16 + ((jT >> 1) << 3) + (lane & 7)) * ROWB
                + (uint32_t)((jT & 1) << 4);

    const int g  = lane >> 2;
    const int c2 = (lane & 3) * 2;

    for (int n = 0; n < ntiles; ++n) {
        const int tl = slot + n * NSLOT;
        const int bb = tl >> 4;
        const int t0 = (tl & 15) << 7;

        float acc[2][8][4];
        #pragma unroll
        for (int mt = 0; mt < 2; ++mt)
            #pragma unroll
            for (int nt = 0; nt < 8; ++nt)
                #pragma unroll
                for (int q = 0; q < 4; ++q) acc[mt][nt][q] = 0.f;

        // A fragment base (uint4 index): (tl*8 + mb)*11*32 + ks*32 + lane
        const uint32_t iA0 = (uint32_t)(tl * 8 + mb0) * (NKS * 32) + lane;
        const uint32_t iA1 = iA0 + NKS * 32;

        #pragma unroll 1
        for (int ks = 0; ks < NKS; ++ks) {
            uint32_t ko = (uint32_t)ks * 32;
            // A fragments straight from gmem (coalesced 512B per LDG.128)
            uint4 Ah0 = __ldg(&g_zf[0][iA0 + ko]);
            uint4 Ah1 = __ldg(&g_zf[0][iA1 + ko]);
            uint4 Al0 = __ldg(&g_zf[1][iA0 + ko]);
            uint4 Al1 = __ldg(&g_zf[1][iA1 + ko]);

            uint32_t kb = (uint32_t)ks * 32u;
            // phase 1: B hi, do hi*hi + lo*hi
            uint32_t Bh[4][4];
            #pragma unroll
            for (int p = 0; p < 4; ++p)
                LDSM4(Bh[p], sb + SM_WHI + bOff[p] + kb);
            #pragma unroll
            for (int nt = 0; nt < 8; ++nt) {
                uint32_t b0 = Bh[nt >> 1][(nt & 1) << 1];
                uint32_t b1 = Bh[nt >> 1][((nt & 1) << 1) + 1];
                MMA16816V(acc[0][nt], Ah0, b0, b1);
                MMA16816V(acc[1][nt], Ah1, b0, b1);
                MMA16816V(acc[0][nt], Al0, b0, b1);
                MMA16816V(acc[1][nt], Al1, b0, b1);
            }
            // phase 2: B lo (Bh dead), hi*lo
            uint32_t Bl[4][4];
            #pragma unroll
            for (int p = 0; p < 4; ++p)
                LDSM4(Bl[p], sb + SM_WLO + bOff[p] + kb);
            #pragma unroll
            for (int nt = 0; nt < 8; ++nt) {
                uint32_t b0 = Bl[nt >> 1][(nt & 1) << 1];
                uint32_t b1 = Bl[nt >> 1][((nt & 1) << 1) + 1];
                MMA16816V(acc[0][nt], Ah0, b0, b1);
                MMA16816V(acc[1][nt], Ah1, b0, b1);
            }
        }

        // ---- epilogue: bias + store ----
        #pragma unroll
        for (int mt = 0; mt < 2; ++mt) {
            size_t row = (size_t)bb * S_ + t0 + warp_m + mt * 16 + g;
            #pragma unroll
            for (int nt = 0; nt < 8; ++nt) {
                int ncol = warp_n + nt * 8 + c2;
                float bi0 = biasS[ncol], bi1 = biasS[ncol + 1];
                float* p0 = out + row * O_ + chunk * OCH + ncol;
                *(float2*)p0 = make_float2(acc[mt][nt][0] + bi0,
                                           acc[mt][nt][1] + bi1);
                *(float2*)(p0 + 8 * O_) = make_float2(acc[mt][nt][2] + bi0,
                                                      acc[mt][nt][3] + bi1);
            }
        }
    }
}

extern "C" void kernel_launch(void* const* d_in, const int* in_sizes, int n_in,
                              void* d_out, int out_size) {
    const float* x    = (const float*)d_in[0];  // (32, 2048, 7)
    const float* W    = (const float*)d_in[1];  // (512, 56, 3)
    const float* bias = (const float*)d_in[2];  // (512,)
    float* out = (float*)d_out;                 // (32, 2048, 512)

    cudaFuncSetAttribute(conv_hmma_kernel,
                         cudaFuncAttributeMaxDynamicSharedMemorySize, SM_TOTAL);

    dim3 pgrid(S_ / TT, B_);   // (16, 32)
    zprep_kernel<<<pgrid, NTH>>>(x, W);
    conv_hmma_kernel<<<NSLOT * NCHUNK, NTH, SM_TOTAL>>>(bias, out);
}

// round 17
// speedup vs baseline: 2.0027x; 1.2156x over previous
#include <cuda_runtime.h>
#include <cuda_fp16.h>
#include <cstdint>
#include <cstddef>

// ---------------- problem constants ----------------
#define B_    32
#define S_    2048
#define C_    7
#define O_    512
#define KLOG  168          // real K, k = i*3+h, i = c*8+m
#define KP    176          // padded K (11 ksteps of 16)
#define NKS   11
#define TT    128          // t per tile (M)
#define OCH   128          // o per chunk (N)
#define NCHUNK 4
#define NSLOT 74           // 74*4 = 296 CTAs = 2/SM
#define NTILE 512          // t-tiles per chunk (32 b * 16)
#define NTH   256

#define ROWB  368          // smem fp16 row stride for W (16B-aligned, conflict-free)

#define XSROWS 298
#define XSN   (XSROWS*C_)  // 2086 floats

// ---------------- main-kernel smem (47.6KB) ----------------
#define SM_BIAS  0                      // 512B
#define SM_WHI   512                    // 128*368 = 47104
#define SM_TOTAL (SM_WHI + 47104)       // 47616

// W hi only: [o=512][k=176] fp16
__device__ __half g_Wh[512 * KP];
// z in m16n8k16 A-FRAGMENT order (fp16 hi/lo):
//   g_zf[half][ (bt*8 + mb)*11 + ks ][lane] : uint4 = frag words r0..r3
__device__ uint4 g_zf[2][NTILE * 8 * NKS * 32];

// ---------------- prep: smem-staged, writes fragment-ordered z + W hi ----
__global__ __launch_bounds__(NTH, 4)
void zprep_kernel(const float* __restrict__ x, const float* __restrict__ W) {
    __shared__ float xs[XSN];
    __shared__ int   koff[KP];
    __shared__ int   kh[KP];

    const int tid = threadIdx.x;
    const int t0  = blockIdx.x << 7;
    const int bb  = blockIdx.y;
    const int bt  = (bb << 4) + blockIdx.x;

    // coalesced stage of the modular x window (proven R5/R13)
    {
        const float* xb = x + (size_t)bb * S_ * C_;
        int g0 = ((t0 - (KLOG + 1)) & (S_ - 1)) * C_;
        #pragma unroll
        for (int f = tid; f < XSN; f += NTH) {
            int g = g0 + f;
            if (g >= S_ * C_) g -= S_ * C_;
            xs[f] = __ldg(&xb[g]);
        }
    }
    if (tid < KP) {
        int k = tid, i = k / 3, h = k - 3 * i, m = i & 7, c = i >> 3;
        koff[k] = (k < KLOG) ? ((h + KLOG - 24 * m) * C_ + c) : 0;
        kh[k]   = (k < KLOG) ? h : 3;       // sentinel: vm bit 3 always 0
    }

    // W hi, done by the tx==0 CTAs (32 CTAs x 16 o-rows each)
    if (blockIdx.x == 0) {
        for (int e = tid; e < 16 * KP; e += NTH) {
            int o = (bb << 4) + e / KP;
            int k = e % KP;
            float w = (k < KLOG) ? __ldg(&W[o * KLOG + k]) : 0.f;
            g_Wh[o * KP + k] = __float2half_rn(w);
        }
    }
    __syncthreads();

    // build fragments: task = (mb, ks, lane) -> one uint4 per half
    for (int e = tid; e < 8 * NKS * 32; e += NTH) {
        int lane = e & 31;
        int rest = e >> 5;
        int ks = rest % NKS;
        int mb = rest / NKS;
        int g  = lane >> 2, tg = lane & 3;
        int lrA = (mb << 4) + g;           // local z row (0..127)
        int lrB = lrA + 8;
        uint32_t vmA = 0, vmB = 0;
        {
            int sA = t0 + lrA - 1, sB = t0 + lrB - 1;
            #pragma unroll
            for (int h = 0; h < 3; ++h) {
                if (((sA + h) & (S_ - 1)) >= KLOG) vmA |= (1u << h);
                if (((sB + h) & (S_ - 1)) >= KLOG) vmB |= (1u << h);
            }
        }
        const float* xrA = xs + lrA * C_;
        const float* xrB = xs + lrB * C_;
        int kb = (ks << 4) + (tg << 1);
        uint32_t hiw[4], low[4];
        #pragma unroll
        for (int r = 0; r < 4; ++r) {
            int k0 = kb + ((r >> 1) << 3);      // +8 for r2,r3
            int k1 = k0 + 1;
            const float* xr = (r & 1) ? xrB : xrA;
            uint32_t vm = (r & 1) ? vmB : vmA;
            float v0 = ((vm >> kh[k0]) & 1) ? xr[koff[k0]] : 0.f;
            float v1 = ((vm >> kh[k1]) & 1) ? xr[koff[k1]] : 0.f;
            __half2 h2 = __floats2half2_rn(v0, v1);      // k0 in low half
            float2 hb  = __half22float2(h2);
            __half2 l2 = __floats2half2_rn(v0 - hb.x, v1 - hb.y);
            hiw[r] = *(uint32_t*)&h2;
            low[r] = *(uint32_t*)&l2;
        }
        uint32_t idx = (uint32_t)((bt * 8 + mb) * NKS + ks) * 32 + lane;
        g_zf[0][idx] = make_uint4(hiw[0], hiw[1], hiw[2], hiw[3]);
        g_zf[1][idx] = make_uint4(low[0], low[1], low[2], low[3]);
    }
}

// ---------------- PTX helpers ----------------
#define CP_COMMIT()  asm volatile("cp.async.commit_group;")
#define CP_WAIT0()   asm volatile("cp.async.wait_group 0;")

#define LDSM4(r, addr) \
    asm volatile("ldmatrix.sync.aligned.m8n8.x4.shared.b16 {%0,%1,%2,%3}, [%4];" \
        : "=r"((r)[0]), "=r"((r)[1]), "=r"((r)[2]), "=r"((r)[3]) : "r"(addr))

#define MMA16816V(d, av, b0, b1) \
    asm volatile("mma.sync.aligned.m16n8k16.row.col.f32.f16.f16.f32 " \
        "{%0,%1,%2,%3},{%4,%5,%6,%7},{%8,%9},{%0,%1,%2,%3};" \
        : "+f"((d)[0]), "+f"((d)[1]), "+f"((d)[2]), "+f"((d)[3]) \
        : "r"((av).x), "r"((av).y), "r"((av).z), "r"((av).w), "r"(b0), "r"(b1))

__global__ __launch_bounds__(NTH, 2)
void conv_hmma_kernel(const float* __restrict__ bias,
                      float* __restrict__ out) {
    extern __shared__ char smem[];
    const uint32_t sb = (uint32_t)__cvta_generic_to_shared(smem);
    const int tid  = threadIdx.x;
    const int lane = tid & 31;
    const int wid  = tid >> 5;
    const int chunk = blockIdx.x & 3;
    const int slot  = blockIdx.x >> 2;
    const int ntiles = (NTILE - slot + NSLOT - 1) / NSLOT;

    float* biasS = (float*)(smem + SM_BIAS);
    for (int j = tid; j < OCH; j += NTH) biasS[j] = bias[chunk * OCH + j];

    // stage W hi slice for this chunk: 128 rows x 22 x 16B
    {
        const char* wsrc = (const char*)g_Wh;
        for (int f = tid; f < 128 * 22; f += NTH) {
            int n = f / 22, seg = f - n * 22;
            const char* src = wsrc + (size_t)(chunk * OCH + n) * (KP * 2) + seg * 16;
            uint32_t dst = sb + SM_WHI + (uint32_t)n * ROWB + seg * 16;
            asm volatile("cp.async.cg.shared.global [%0], [%1], 16;"
                         :: "r"(dst), "l"(src));
        }
    }
    CP_COMMIT();
    CP_WAIT0();
    __syncthreads();          // W + bias visible; the ONLY barrier

    const int warp_m = (wid & 3) * 32;
    const int warp_n = (wid >> 2) * 64;
    const int mb0    = 2 * (wid & 3);     // first m16-block of this warp

    // B ldmatrix per-lane offsets
    const int jT = lane >> 3;
    uint32_t bOff[4];
    #pragma unroll
    for (int p = 0; p < 4; ++p)
        bOff[p] = (uint32_t)(warp_n + p * 16 + ((jT >> 1) << 3) + (lane & 7)) * ROWB
                + (uint32_t)((jT & 1) << 4);

    const int g  = lane >> 2;
    const int c2 = (lane & 3) * 2;

    for (int n = 0; n < ntiles; ++n) {
        const int tl = slot + n * NSLOT;
        const int bb = tl >> 4;
        const int t0 = (tl & 15) << 7;

        float acc[2][8][4];
        #pragma unroll
        for (int mt = 0; mt < 2; ++mt)
            #pragma unroll
            for (int nt = 0; nt < 8; ++nt)
                #pragma unroll
                for (int q = 0; q < 4; ++q) acc[mt][nt][q] = 0.f;

        const uint32_t iA0 = (uint32_t)(tl * 8 + mb0) * (NKS * 32) + lane;
        const uint32_t iA1 = iA0 + NKS * 32;

        #pragma unroll 1
        for (int ks = 0; ks < NKS; ++ks) {
            uint32_t ko = (uint32_t)ks * 32;
            // A fragments straight from gmem (coalesced 512B per LDG.128)
            uint4 Ah0 = __ldg(&g_zf[0][iA0 + ko]);
            uint4 Ah1 = __ldg(&g_zf[0][iA1 + ko]);
            uint4 Al0 = __ldg(&g_zf[1][iA0 + ko]);
            uint4 Al1 = __ldg(&g_zf[1][iA1 + ko]);

            uint32_t kb = (uint32_t)ks * 32u;
            uint32_t Bh[4][4];
            #pragma unroll
            for (int p = 0; p < 4; ++p)
                LDSM4(Bh[p], sb + SM_WHI + bOff[p] + kb);
            #pragma unroll
            for (int nt = 0; nt < 8; ++nt) {
                uint32_t b0 = Bh[nt >> 1][(nt & 1) << 1];
                uint32_t b1 = Bh[nt >> 1][((nt & 1) << 1) + 1];
                MMA16816V(acc[0][nt], Ah0, b0, b1);
                MMA16816V(acc[1][nt], Ah1, b0, b1);
                MMA16816V(acc[0][nt], Al0, b0, b1);
                MMA16816V(acc[1][nt], Al1, b0, b1);
            }
        }

        // ---- epilogue: bias + store ----
        #pragma unroll
        for (int mt = 0; mt < 2; ++mt) {
            size_t row = (size_t)bb * S_ + t0 + warp_m + mt * 16 + g;
            #pragma unroll
            for (int nt = 0; nt < 8; ++nt) {
                int ncol = warp_n + nt * 8 + c2;
                float bi0 = biasS[ncol], bi1 = biasS[ncol + 1];
                float* p0 = out + row * O_ + chunk * OCH + ncol;
                *(float2*)p0 = make_float2(acc[mt][nt][0] + bi0,
                                           acc[mt][nt][1] + bi1);
                *(float2*)(p0 + 8 * O_) = make_float2(acc[mt][nt][2] + bi0,
                                                      acc[mt][nt][3] + bi1);
            }
        }
    }
}

extern "C" void kernel_launch(void* const* d_in, const int* in_sizes, int n_in,
                              void* d_out, int out_size) {
    const float* x    = (const float*)d_in[0];  // (32, 2048, 7)
    const float* W    = (const float*)d_in[1];  // (512, 56, 3)
    const float* bias = (const float*)d_in[2];  // (512,)
    float* out = (float*)d_out;                 // (32, 2048, 512)

    cudaFuncSetAttribute(conv_hmma_kernel,
                         cudaFuncAttributeMaxDynamicSharedMemorySize, SM_TOTAL);

    dim3 pgrid(S_ / TT, B_);   // (16, 32)
    zprep_kernel<<<pgrid, NTH>>>(x, W);
    conv_hmma_kernel<<<NSLOT * NCHUNK, NTH, SM_TOTAL>>>(bias, out);
}